// round 1
// baseline (speedup 1.0000x reference)
#include <cuda_runtime.h>
#include <cuda_bf16.h>

// Problem constants
#define D_MODEL 1024
#define NUM_HEADS 16
#define HEAD_DIM 64
#define BATCH 2
#define SEQ 2048
#define NTOK (BATCH * SEQ)        // 4096
#define D3 (3 * D_MODEL)          // 3072

// Scratch (no cudaMalloc allowed)
__device__ float g_qkv[NTOK * D3];      // [token][3*D]  Q|K|V
__device__ float g_ctx[NTOK * D_MODEL]; // [token][D]

// ---------------------------------------------------------------------------
// Generic SGEMM + bias: C[M,N] = A[M,K] @ B[K,N] + bias[N]
// 128x128 tile, BK=8, 256 threads, 8x8 micro-tile per thread.
// Requires M%128==0, N%128==0, K%8==0 (true for all our shapes).
// ---------------------------------------------------------------------------
#define BM 128
#define BN 128
#define BKK 8

__global__ __launch_bounds__(256) void sgemm_bias_kernel(
    const float* __restrict__ A, const float* __restrict__ B,
    const float* __restrict__ bias, float* __restrict__ C,
    int M, int N, int K)
{
    __shared__ float As[BKK][BM];
    __shared__ float Bs[BKK][BN];

    const int tid = threadIdx.x;
    const int bm = blockIdx.y * BM;
    const int bn = blockIdx.x * BN;

    // A tile load: 128 rows x 8 cols, one float4 per thread
    const int arow = tid >> 1;           // 0..127
    const int acol = (tid & 1) * 4;      // 0 or 4
    // B tile load: 8 rows x 128 cols, one float4 per thread
    const int brow = tid >> 5;           // 0..7
    const int bcol = (tid & 31) * 4;     // 0..124

    const int trow = (tid >> 4) * 8;     // 0..120
    const int tcol = (tid & 15) * 8;     // 0..120

    float acc[8][8];
    #pragma unroll
    for (int i = 0; i < 8; i++)
        #pragma unroll
        for (int j = 0; j < 8; j++) acc[i][j] = 0.0f;

    for (int kt = 0; kt < K; kt += BKK) {
        float4 a4 = *(const float4*)&A[(size_t)(bm + arow) * K + kt + acol];
        As[acol + 0][arow] = a4.x;
        As[acol + 1][arow] = a4.y;
        As[acol + 2][arow] = a4.z;
        As[acol + 3][arow] = a4.w;
        *(float4*)&Bs[brow][bcol] =
            *(const float4*)&B[(size_t)(kt + brow) * N + bn + bcol];
        __syncthreads();

        #pragma unroll
        for (int k = 0; k < BKK; k++) {
            float4 ra0 = *(const float4*)&As[k][trow];
            float4 ra1 = *(const float4*)&As[k][trow + 4];
            float4 rb0 = *(const float4*)&Bs[k][tcol];
            float4 rb1 = *(const float4*)&Bs[k][tcol + 4];
            float ra[8] = {ra0.x, ra0.y, ra0.z, ra0.w, ra1.x, ra1.y, ra1.z, ra1.w};
            float rb[8] = {rb0.x, rb0.y, rb0.z, rb0.w, rb1.x, rb1.y, rb1.z, rb1.w};
            #pragma unroll
            for (int i = 0; i < 8; i++)
                #pragma unroll
                for (int j = 0; j < 8; j++)
                    acc[i][j] += ra[i] * rb[j];
        }
        __syncthreads();
    }

    #pragma unroll
    for (int i = 0; i < 8; i++) {
        const int row = bm + trow + i;
        #pragma unroll
        for (int j = 0; j < 8; j += 4) {
            const int col = bn + tcol + j;
            float4 o;
            o.x = acc[i][j + 0] + bias[col + 0];
            o.y = acc[i][j + 1] + bias[col + 1];
            o.z = acc[i][j + 2] + bias[col + 2];
            o.w = acc[i][j + 3] + bias[col + 3];
            *(float4*)&C[(size_t)row * N + col] = o;
        }
    }
}

// ---------------------------------------------------------------------------
// Attention: one thread = one query, 128 queries per block, online softmax
// over 32-key tiles staged in shared memory.
// grid = (SEQ/128, NUM_HEADS, BATCH)
// ---------------------------------------------------------------------------
#define KT 32

__global__ __launch_bounds__(128) void attn_kernel(
    const float* __restrict__ qkv, const int* __restrict__ mask,
    float* __restrict__ ctx)
{
    __shared__ float Ks[KT][HEAD_DIM];
    __shared__ float Vs[KT][HEAD_DIM];
    __shared__ int   Ms[KT];

    const int h = blockIdx.y;
    const int b = blockIdx.z;
    const int tid = threadIdx.x;
    const int q_idx = blockIdx.x * 128 + tid;
    const int tbase = b * SEQ;
    const float scale = 0.125f;  // 1/sqrt(64)

    // load this thread's query row into registers
    float4 q4[16];
    const float* qptr = qkv + (size_t)(tbase + q_idx) * D3 + h * HEAD_DIM;
    #pragma unroll
    for (int i = 0; i < 16; i++) q4[i] = *(const float4*)(qptr + i * 4);

    float accv[HEAD_DIM];
    #pragma unroll
    for (int d = 0; d < HEAD_DIM; d++) accv[d] = 0.0f;
    float m = -1e30f, l = 0.0f;

    for (int kt = 0; kt < SEQ; kt += KT) {
        __syncthreads();  // previous tile fully consumed
        // stage K,V tile: KT*HEAD_DIM = 2048 floats each = 512 float4 each.
        // 128 threads -> 4 float4 from K and 4 from V per thread.
        #pragma unroll
        for (int i = 0; i < 4; i++) {
            const int f = tid + i * 128;          // float4 index 0..511
            const int row = f >> 4;               // 16 float4 per row
            const int col4 = (f & 15) * 4;
            const size_t src =
                (size_t)(tbase + kt + row) * D3 + h * HEAD_DIM + col4;
            *(float4*)&Ks[row][col4] = *(const float4*)&qkv[src + D_MODEL];
            *(float4*)&Vs[row][col4] = *(const float4*)&qkv[src + 2 * D_MODEL];
        }
        if (tid < KT) Ms[tid] = mask[b * SEQ + kt + tid];
        __syncthreads();

        // scores for this tile
        float s_arr[KT];
        float tmax = -1e30f;
        #pragma unroll
        for (int kk = 0; kk < KT; kk++) {
            float s = 0.0f;
            #pragma unroll
            for (int d4 = 0; d4 < 16; d4++) {
                float4 kv = *(const float4*)&Ks[kk][d4 * 4];
                s += q4[d4].x * kv.x + q4[d4].y * kv.y +
                     q4[d4].z * kv.z + q4[d4].w * kv.w;
            }
            s *= scale;
            if (Ms[kk] == 0) s = -1e30f;
            s_arr[kk] = s;
            tmax = fmaxf(tmax, s);
        }

        const float m_new = fmaxf(m, tmax);
        const float corr = __expf(m - m_new);
        m = m_new;
        l *= corr;
        #pragma unroll
        for (int d = 0; d < HEAD_DIM; d++) accv[d] *= corr;

        #pragma unroll
        for (int kk = 0; kk < KT; kk++) {
            const float p = __expf(s_arr[kk] - m_new);
            l += p;
            #pragma unroll
            for (int d4 = 0; d4 < 16; d4++) {
                float4 v = *(const float4*)&Vs[kk][d4 * 4];
                accv[d4 * 4 + 0] += p * v.x;
                accv[d4 * 4 + 1] += p * v.y;
                accv[d4 * 4 + 2] += p * v.z;
                accv[d4 * 4 + 3] += p * v.w;
            }
        }
    }

    const float inv = 1.0f / l;
    float* optr = ctx + (size_t)(tbase + q_idx) * D_MODEL + h * HEAD_DIM;
    #pragma unroll
    for (int d4 = 0; d4 < 16; d4++) {
        float4 o;
        o.x = accv[d4 * 4 + 0] * inv;
        o.y = accv[d4 * 4 + 1] * inv;
        o.z = accv[d4 * 4 + 2] * inv;
        o.w = accv[d4 * 4 + 3] * inv;
        *(float4*)(optr + d4 * 4) = o;
    }
}

// ---------------------------------------------------------------------------
// Launch
// ---------------------------------------------------------------------------
extern "C" void kernel_launch(void* const* d_in, const int* in_sizes, int n_in,
                              void* d_out, int out_size)
{
    const float* x     = (const float*)d_in[0];  // [B,S,D]
    const int*   mask  = (const int*)d_in[1];    // [B,S]
    const float* Wqkv  = (const float*)d_in[2];  // [D,3D]
    const float* bqkv  = (const float*)d_in[3];  // [3D]
    const float* Wproj = (const float*)d_in[4];  // [D,D]
    const float* bproj = (const float*)d_in[5];  // [D]
    float* out = (float*)d_out;                  // [B,S,D]

    float *qkv, *ctx;
    cudaGetSymbolAddress((void**)&qkv, g_qkv);
    cudaGetSymbolAddress((void**)&ctx, g_ctx);

    // 1) QKV GEMM: [4096,1024] @ [1024,3072] + b -> g_qkv
    {
        dim3 grid(D3 / BN, NTOK / BM);
        sgemm_bias_kernel<<<grid, 256>>>(x, Wqkv, bqkv, qkv, NTOK, D3, D_MODEL);
    }
    // 2) Attention -> g_ctx
    {
        dim3 grid(SEQ / 128, NUM_HEADS, BATCH);
        attn_kernel<<<grid, 128>>>(qkv, mask, ctx);
    }
    // 3) Output projection: [4096,1024] @ [1024,1024] + b -> out
    {
        dim3 grid(D_MODEL / BN, NTOK / BM);
        sgemm_bias_kernel<<<grid, 256>>>(ctx, Wproj, bproj, out, NTOK, D_MODEL, D_MODEL);
    }
}

// round 3
// speedup vs baseline: 3.6424x; 3.6424x over previous
#include <cuda_runtime.h>
#include <cstdint>

// Problem constants
#define D_MODEL 1024
#define NUM_HEADS 16
#define HEAD_DIM 64
#define BATCH 2
#define SEQ 2048
#define NTOK 4096
#define D3 3072

// ---------------------------------------------------------------------------
// Scratch (no cudaMalloc allowed)
// ---------------------------------------------------------------------------
__device__ float g_qkv[NTOK * D3];        // [token][3*D]  Q|K|V (fp32)
__device__ float g_ctx[NTOK * D_MODEL];   // [token][D]
__device__ float g_vt[NTOK * D_MODEL];    // [b*H+h][hd][SEQ]  V transposed (tf32)

// ---------------------------------------------------------------------------
// tf32 helpers (plain PTX, works on bare sm_103 target)
// ---------------------------------------------------------------------------
__device__ __forceinline__ uint32_t f2tf(float f) {
    uint32_t u; asm("cvt.rna.tf32.f32 %0, %1;" : "=r"(u) : "f"(f)); return u;
}
__device__ __forceinline__ float f2tf_f(float f) { return __uint_as_float(f2tf(f)); }

// mma.sync m16n8k8 tf32: D = A*B + D
__device__ __forceinline__ void mma_tf32(float d[4], const uint32_t a[4],
                                         const uint32_t b[2]) {
    asm volatile(
        "mma.sync.aligned.m16n8k8.row.col.f32.tf32.tf32.f32 "
        "{%0,%1,%2,%3}, {%4,%5,%6,%7}, {%8,%9}, {%0,%1,%2,%3};"
        : "+f"(d[0]), "+f"(d[1]), "+f"(d[2]), "+f"(d[3])
        : "r"(a[0]), "r"(a[1]), "r"(a[2]), "r"(a[3]), "r"(b[0]), "r"(b[1]));
}

// ---------------------------------------------------------------------------
// GEMM (tf32 mma): C[M,N] = A[M,K] @ W[K,N] + bias[N]
// 128x128 tile, BK=32, 256 threads (8 warps, 4x2 grid of 32x64 warp tiles)
// ---------------------------------------------------------------------------
#define BM 128
#define BN 128
#define BK 32
#define AS_STRIDE 36    // 36 mod 32 == 4  -> conflict-free A-frag LDS
#define BS_STRIDE 136   // 136 mod 32 == 8 -> conflict-free B-frag LDS
#define GEMM_SMEM ((128 * AS_STRIDE + BK * BS_STRIDE) * 4)

__global__ __launch_bounds__(256) void gemm_tf32_kernel(
    const float* __restrict__ A, const float* __restrict__ W,
    const float* __restrict__ bias, float* __restrict__ C,
    int M, int N, int K)
{
    extern __shared__ float sm[];
    float* As = sm;                       // [128][36]
    float* Bs = sm + 128 * AS_STRIDE;     // [32][136]  (row = k, col = n)

    const int tid  = threadIdx.x;
    const int lane = tid & 31;
    const int wid  = tid >> 5;
    const int wm = (wid >> 1) * 32;       // warp M offset (0..96)
    const int wn = (wid & 1) * 64;        // warp N offset (0/64)
    const int bm = blockIdx.y * BM;
    const int bn = blockIdx.x * BN;
    const int lq = lane >> 2;             // lane / 4
    const int lr = lane & 3;              // lane % 4

    float acc[2][8][4];
#pragma unroll
    for (int i = 0; i < 2; i++)
#pragma unroll
        for (int j = 0; j < 8; j++)
#pragma unroll
            for (int e = 0; e < 4; e++) acc[i][j][e] = 0.0f;

    for (int kt = 0; kt < K; kt += BK) {
        // stage A tile [128][32] (tf32-rounded)
#pragma unroll
        for (int i = 0; i < 4; i++) {
            int f = tid + i * 256;
            int row = f >> 3, c4 = (f & 7) * 4;
            float4 v = *(const float4*)&A[(size_t)(bm + row) * K + kt + c4];
            float* d = &As[row * AS_STRIDE + c4];
            d[0] = f2tf_f(v.x); d[1] = f2tf_f(v.y);
            d[2] = f2tf_f(v.z); d[3] = f2tf_f(v.w);
        }
        // stage B tile [32 k][128 n]
#pragma unroll
        for (int i = 0; i < 4; i++) {
            int f = tid + i * 256;
            int row = f >> 5, c4 = (f & 31) * 4;
            float4 v = *(const float4*)&W[(size_t)(kt + row) * N + bn + c4];
            float* d = &Bs[row * BS_STRIDE + c4];
            d[0] = f2tf_f(v.x); d[1] = f2tf_f(v.y);
            d[2] = f2tf_f(v.z); d[3] = f2tf_f(v.w);
        }
        __syncthreads();

#pragma unroll
        for (int ks = 0; ks < 4; ks++) {
            uint32_t af[2][4];
#pragma unroll
            for (int i = 0; i < 2; i++) {
                const float* p = &As[(wm + i * 16 + lq) * AS_STRIDE + ks * 8 + lr];
                af[i][0] = __float_as_uint(p[0]);
                af[i][1] = __float_as_uint(p[8 * AS_STRIDE]);
                af[i][2] = __float_as_uint(p[4]);
                af[i][3] = __float_as_uint(p[8 * AS_STRIDE + 4]);
            }
#pragma unroll
            for (int j = 0; j < 8; j++) {
                uint32_t bf[2];
                const float* p = &Bs[(ks * 8 + lr) * BS_STRIDE + wn + j * 8 + lq];
                bf[0] = __float_as_uint(p[0]);
                bf[1] = __float_as_uint(p[4 * BS_STRIDE]);
                mma_tf32(acc[0][j], af[0], bf);
                mma_tf32(acc[1][j], af[1], bf);
            }
        }
        __syncthreads();
    }

    // epilogue: bias + store (C-fragment layout)
#pragma unroll
    for (int i = 0; i < 2; i++) {
        const int r0 = bm + wm + i * 16 + lq;
#pragma unroll
        for (int j = 0; j < 8; j++) {
            const int col = bn + wn + j * 8 + lr * 2;
            const float b0 = bias[col], b1 = bias[col + 1];
            float2 o0 = make_float2(acc[i][j][0] + b0, acc[i][j][1] + b1);
            float2 o1 = make_float2(acc[i][j][2] + b0, acc[i][j][3] + b1);
            *(float2*)&C[(size_t)r0 * N + col] = o0;
            *(float2*)&C[(size_t)(r0 + 8) * N + col] = o1;
        }
    }
}

// ---------------------------------------------------------------------------
// V transpose pre-pass: g_qkv V region -> g_vt[bh][hd][seq] (tf32-rounded)
// grid (SEQ/32, HEAD_DIM/32, B*H), block (32,8)
// ---------------------------------------------------------------------------
__global__ void vt_kernel()
{
    __shared__ float t[32][33];
    const int s0 = blockIdx.x * 32, hd0 = blockIdx.y * 32, bh = blockIdx.z;
    const int b = bh >> 4, h = bh & 15;
    const int tx = threadIdx.x, ty = threadIdx.y;
#pragma unroll
    for (int j = 0; j < 4; j++) {
        int s = s0 + ty + j * 8;
        t[ty + j * 8][tx] = g_qkv[(size_t)(b * SEQ + s) * D3 + 2 * D_MODEL +
                                  h * HEAD_DIM + hd0 + tx];
    }
    __syncthreads();
#pragma unroll
    for (int j = 0; j < 4; j++) {
        int hd = hd0 + ty + j * 8;
        g_vt[((size_t)bh * HEAD_DIM + hd) * SEQ + s0 + tx] =
            f2tf_f(t[tx][ty + j * 8]);
    }
}

// ---------------------------------------------------------------------------
// Attention (tf32 mma flash): 64 queries/CTA, 64-key tiles, online softmax.
// grid (SEQ/64, H, B), block 128 (4 warps x 16 query rows).
// ---------------------------------------------------------------------------
#define ATS 68          // 68 mod 32 == 4 -> conflict-free frag LDS
#define ATT_SMEM ((4 * 64 * ATS + 64) * 4)

__global__ __launch_bounds__(128) void attn_mma_kernel(const int* __restrict__ mask)
{
    extern __shared__ float sm[];
    float* Qs = sm;                       // [64][68]
    float* Ks = sm + 64 * ATS;            // [64 key][68 hd]
    float* Vs = sm + 2 * 64 * ATS;        // [64 hd][68 key]
    float* Ps = sm + 3 * 64 * ATS;        // [64 q][68 key]
    float* mb = sm + 4 * 64 * ATS;        // [64] additive mask bias

    const int tid = threadIdx.x, lane = tid & 31, w = tid >> 5;
    const int lq = lane >> 2, lr = lane & 3;
    const int h = blockIdx.y, b = blockIdx.z;
    const int q0 = blockIdx.x * 64;
    const int bh = b * NUM_HEADS + h;
    const size_t tokbase = (size_t)b * SEQ;
    const float scale = 0.125f;           // 1/sqrt(64)

    // stage Q tile
#pragma unroll
    for (int i = 0; i < 8; i++) {
        int f = tid + i * 128;
        int row = f >> 4, c4 = (f & 15) * 4;
        float4 v = *(const float4*)&g_qkv[(tokbase + q0 + row) * D3 +
                                          h * HEAD_DIM + c4];
        float* d = &Qs[row * ATS + c4];
        d[0] = f2tf_f(v.x); d[1] = f2tf_f(v.y);
        d[2] = f2tf_f(v.z); d[3] = f2tf_f(v.w);
    }
    __syncthreads();

    // Q fragments (resident all CTA lifetime)
    uint32_t qa[8][4];
    {
        const int r = w * 16 + lq;
#pragma unroll
        for (int ks = 0; ks < 8; ks++) {
            const float* p = &Qs[r * ATS + ks * 8 + lr];
            qa[ks][0] = __float_as_uint(p[0]);
            qa[ks][1] = __float_as_uint(p[8 * ATS]);
            qa[ks][2] = __float_as_uint(p[4]);
            qa[ks][3] = __float_as_uint(p[8 * ATS + 4]);
        }
    }

    float O[8][4];
#pragma unroll
    for (int j = 0; j < 8; j++)
#pragma unroll
        for (int e = 0; e < 4; e++) O[j][e] = 0.0f;
    float m0 = -1e30f, m1 = -1e30f, l0 = 0.0f, l1 = 0.0f;

    for (int kt = 0; kt < SEQ; kt += 64) {
        __syncthreads();  // previous tile's Ks/Vs fully consumed
        // stage K tile [key][hd] and V^T tile [hd][key]
#pragma unroll
        for (int i = 0; i < 8; i++) {
            int f = tid + i * 128;
            int row = f >> 4, c4 = (f & 15) * 4;
            float4 v = *(const float4*)&g_qkv[(tokbase + kt + row) * D3 +
                                              D_MODEL + h * HEAD_DIM + c4];
            float* d = &Ks[row * ATS + c4];
            d[0] = f2tf_f(v.x); d[1] = f2tf_f(v.y);
            d[2] = f2tf_f(v.z); d[3] = f2tf_f(v.w);
            float4 u = *(const float4*)&g_vt[((size_t)bh * HEAD_DIM + row) * SEQ +
                                             kt + c4];
            float* e = &Vs[row * ATS + c4];
            e[0] = u.x; e[1] = u.y; e[2] = u.z; e[3] = u.w;  // already tf32
        }
        if (tid < 64)
            mb[tid] = (mask[b * SEQ + kt + tid] == 0) ? -1e30f : 0.0f;
        __syncthreads();

        // S = Q @ K^T  (C frag: rows lq / lq+8, cols j*8 + 2*lr + {0,1})
        float s[8][4];
#pragma unroll
        for (int j = 0; j < 8; j++)
#pragma unroll
            for (int e = 0; e < 4; e++) s[j][e] = 0.0f;
#pragma unroll
        for (int ks = 0; ks < 8; ks++) {
#pragma unroll
            for (int j = 0; j < 8; j++) {
                uint32_t bf[2];
                const float* p = &Ks[(j * 8 + lq) * ATS + ks * 8 + lr];
                bf[0] = __float_as_uint(p[0]);
                bf[1] = __float_as_uint(p[4]);
                mma_tf32(s[j], qa[ks], bf);
            }
        }

        // scale + mask + online softmax
        float mx0 = -1e30f, mx1 = -1e30f;
#pragma unroll
        for (int j = 0; j < 8; j++) {
            float2 mbias = *(const float2*)&mb[j * 8 + lr * 2];
            s[j][0] = s[j][0] * scale + mbias.x;
            s[j][1] = s[j][1] * scale + mbias.y;
            s[j][2] = s[j][2] * scale + mbias.x;
            s[j][3] = s[j][3] * scale + mbias.y;
            mx0 = fmaxf(mx0, fmaxf(s[j][0], s[j][1]));
            mx1 = fmaxf(mx1, fmaxf(s[j][2], s[j][3]));
        }
        mx0 = fmaxf(mx0, __shfl_xor_sync(0xffffffffu, mx0, 1));
        mx0 = fmaxf(mx0, __shfl_xor_sync(0xffffffffu, mx0, 2));
        mx1 = fmaxf(mx1, __shfl_xor_sync(0xffffffffu, mx1, 1));
        mx1 = fmaxf(mx1, __shfl_xor_sync(0xffffffffu, mx1, 2));

        const float mn0 = fmaxf(m0, mx0), mn1 = fmaxf(m1, mx1);
        const float c0 = __expf(m0 - mn0), c1 = __expf(m1 - mn1);
        float sum0 = 0.0f, sum1 = 0.0f;
        {
            float* prow = &Ps[(w * 16 + lq) * ATS + lr * 2];
#pragma unroll
            for (int j = 0; j < 8; j++) {
                s[j][0] = __expf(s[j][0] - mn0);
                s[j][1] = __expf(s[j][1] - mn0);
                s[j][2] = __expf(s[j][2] - mn1);
                s[j][3] = __expf(s[j][3] - mn1);
                sum0 += s[j][0] + s[j][1];
                sum1 += s[j][2] + s[j][3];
                prow[j * 8 + 0] = f2tf_f(s[j][0]);
                prow[j * 8 + 1] = f2tf_f(s[j][1]);
                prow[8 * ATS + j * 8 + 0] = f2tf_f(s[j][2]);
                prow[8 * ATS + j * 8 + 1] = f2tf_f(s[j][3]);
            }
        }
        sum0 += __shfl_xor_sync(0xffffffffu, sum0, 1);
        sum0 += __shfl_xor_sync(0xffffffffu, sum0, 2);
        sum1 += __shfl_xor_sync(0xffffffffu, sum1, 1);
        sum1 += __shfl_xor_sync(0xffffffffu, sum1, 2);
        l0 = l0 * c0 + sum0;
        l1 = l1 * c1 + sum1;
        m0 = mn0; m1 = mn1;
#pragma unroll
        for (int j = 0; j < 8; j++) {
            O[j][0] *= c0; O[j][1] *= c0;
            O[j][2] *= c1; O[j][3] *= c1;
        }
        __syncwarp();  // Ps rows are warp-private; order STS before LDS

        // O += P @ V   (A = P[q][key] frags, B = Vs[hd][key])
#pragma unroll
        for (int ks = 0; ks < 8; ks++) {
            uint32_t pa[4];
            const float* pp = &Ps[(w * 16 + lq) * ATS + ks * 8 + lr];
            pa[0] = __float_as_uint(pp[0]);
            pa[1] = __float_as_uint(pp[8 * ATS]);
            pa[2] = __float_as_uint(pp[4]);
            pa[3] = __float_as_uint(pp[8 * ATS + 4]);
#pragma unroll
            for (int j = 0; j < 8; j++) {
                uint32_t bf[2];
                const float* vp = &Vs[(j * 8 + lq) * ATS + ks * 8 + lr];
                bf[0] = __float_as_uint(vp[0]);
                bf[1] = __float_as_uint(vp[4]);
                mma_tf32(O[j], pa, bf);
            }
        }
    }

    // normalize + store ctx
    const float inv0 = 1.0f / l0, inv1 = 1.0f / l1;
    const int r0 = q0 + w * 16 + lq;
#pragma unroll
    for (int j = 0; j < 8; j++) {
        const int col = h * HEAD_DIM + j * 8 + lr * 2;
        float2 o0 = make_float2(O[j][0] * inv0, O[j][1] * inv0);
        float2 o1 = make_float2(O[j][2] * inv1, O[j][3] * inv1);
        *(float2*)&g_ctx[(tokbase + r0) * D_MODEL + col] = o0;
        *(float2*)&g_ctx[(tokbase + r0 + 8) * D_MODEL + col] = o1;
    }
}

// ---------------------------------------------------------------------------
// Launch
// ---------------------------------------------------------------------------
extern "C" void kernel_launch(void* const* d_in, const int* in_sizes, int n_in,
                              void* d_out, int out_size)
{
    const float* x     = (const float*)d_in[0];  // [B,S,D]
    const int*   mask  = (const int*)d_in[1];    // [B,S]
    const float* Wqkv  = (const float*)d_in[2];  // [D,3D]
    const float* bqkv  = (const float*)d_in[3];  // [3D]
    const float* Wproj = (const float*)d_in[4];  // [D,D]
    const float* bproj = (const float*)d_in[5];  // [D]
    float* out = (float*)d_out;                  // [B,S,D]

    float *qkv, *ctx;
    cudaGetSymbolAddress((void**)&qkv, g_qkv);
    cudaGetSymbolAddress((void**)&ctx, g_ctx);

    static bool attr_done = false;
    if (!attr_done) {
        cudaFuncSetAttribute(gemm_tf32_kernel,
                             cudaFuncAttributeMaxDynamicSharedMemorySize,
                             GEMM_SMEM);
        cudaFuncSetAttribute(attn_mma_kernel,
                             cudaFuncAttributeMaxDynamicSharedMemorySize,
                             ATT_SMEM);
        attr_done = true;
    }

    // 1) QKV GEMM: [4096,1024] @ [1024,3072] + b -> g_qkv
    {
        dim3 grid(D3 / BN, NTOK / BM);
        gemm_tf32_kernel<<<grid, 256, GEMM_SMEM>>>(x, Wqkv, bqkv, qkv,
                                                   NTOK, D3, D_MODEL);
    }
    // 2) V transpose pre-pass
    {
        dim3 grid(SEQ / 32, HEAD_DIM / 32, BATCH * NUM_HEADS);
        vt_kernel<<<grid, dim3(32, 8)>>>();
    }
    // 3) Attention -> g_ctx
    {
        dim3 grid(SEQ / 64, NUM_HEADS, BATCH);
        attn_mma_kernel<<<grid, 128, ATT_SMEM>>>(mask);
    }
    // 4) Output projection: [4096,1024] @ [1024,1024] + b -> out
    {
        dim3 grid(D_MODEL / BN, NTOK / BM);
        gemm_tf32_kernel<<<grid, 256, GEMM_SMEM>>>(ctx, Wproj, bproj, out,
                                                   NTOK, D_MODEL, D_MODEL);
    }
}